// round 6
// baseline (speedup 1.0000x reference)
#include <cuda_runtime.h>
#include <stdint.h>

#define NPTS 256
#define DIM  256
#define KNN  16
#define NB   128        // 2 rows per block, 512 threads; blocks independent
#define EPSV 1e-12f

__device__ float    g_part[NB];
__device__ unsigned g_done = 0;

typedef unsigned long long u64;

__global__ __launch_bounds__(512, 1)
void k_fused(const float* __restrict__ yi, const float* __restrict__ yit,
             float* __restrict__ out) {
    __shared__ float    s_n[2][DIM];    // normalized yi rows r0,r1
    __shared__ float    s_t[2][DIM];    // normalized yit rows r0,r1
    __shared__ unsigned sk[2][NPTS];    // d1 bit-keys per row
    __shared__ float    red0[16], red1[16], red2[16];
    __shared__ float4   sh_par[2];      // ia, ic, rn, rt per row
    __shared__ float    sh_ds[2];       // dself per row
    __shared__ float    shredf[16];
    __shared__ unsigned s_last;

    const int t   = threadIdx.x, b = blockIdx.x;
    const int h   = t >> 8;             // half: which row of the pair
    const int col = t & 255;
    const int w   = t >> 5, l = t & 31;
    const int row = 2 * b + h;

    // ---------- Phase A: normalize row `row` (3 sums in one reduction) ----------
    float a = yi [row * DIM + col];
    float c = yit[row * DIM + col];
    float paa = a * a, pcc = c * c, pac = a * c;
    #pragma unroll
    for (int o = 16; o; o >>= 1) {
        paa += __shfl_down_sync(0xffffffffu, paa, o);
        pcc += __shfl_down_sync(0xffffffffu, pcc, o);
        pac += __shfl_down_sync(0xffffffffu, pac, o);
    }
    if (l == 0) { red0[w] = paa; red1[w] = pcc; red2[w] = pac; }
    __syncthreads();
    if ((w & 7) == 0 && l == 0) {       // one thread per half
        float sa = 0.f, sc = 0.f, sac = 0.f;
        #pragma unroll
        for (int m = 0; m < 8; m++) {
            sa  += red0[h * 8 + m];
            sc  += red1[h * 8 + m];
            sac += red2[h * 8 + m];
        }
        float ia = 1.0f / sqrtf(sa + EPSV);
        float ic = 1.0f / sqrtf(sc + EPSV);
        float rn = sa * ia * ia, rt = sc * ic * ic;
        sh_par[h] = make_float4(ia, ic, rn, rt);
        sh_ds[h]  = 0.5f * sqrtf(fmaxf(rn + rt - 2.f * ia * ic * sac, 0.f) + EPSV);
    }
    __syncthreads();
    float4 P = sh_par[h];               // ia, ic, rn, rt of this row
    s_n[h][col] = a * P.x;
    s_t[h][col] = c * P.y;
    __syncthreads();

    // ---------- Phase B: fused column norm + dual dot, even/odd f32x2 packing ----------
    // Thread (h,col) streams raw yi row `col`; packed lanes = (even dim, odd dim).
    const ulonglong2* vr = (const ulonglong2*)(yi + col * DIM);   // 64 x 16B
    const u64* sn = (const u64*)s_n[h];
    const u64* st = (const u64*)s_t[h];
    u64 an0 = 0ull, an1 = 0ull, at0 = 0ull, at1 = 0ull, ss0 = 0ull, ss1 = 0ull;

    #pragma unroll 8
    for (int q = 0; q < DIM / 4; q++) {
        ulonglong2 v = vr[q];           // dims 4q..4q+3
        u64 n0 = sn[2 * q], n1 = sn[2 * q + 1];
        u64 t0 = st[2 * q], t1 = st[2 * q + 1];
        asm("fma.rn.f32x2 %0, %1, %2, %0;" : "+l"(an0) : "l"(n0), "l"(v.x));
        asm("fma.rn.f32x2 %0, %1, %2, %0;" : "+l"(an1) : "l"(n1), "l"(v.y));
        asm("fma.rn.f32x2 %0, %1, %2, %0;" : "+l"(at0) : "l"(t0), "l"(v.x));
        asm("fma.rn.f32x2 %0, %1, %2, %0;" : "+l"(at1) : "l"(t1), "l"(v.y));
        asm("fma.rn.f32x2 %0, %1, %2, %0;" : "+l"(ss0) : "l"(v.x), "l"(v.x));
        asm("fma.rn.f32x2 %0, %1, %2, %0;" : "+l"(ss1) : "l"(v.y), "l"(v.y));
    }
    asm("add.rn.f32x2 %0, %0, %1;" : "+l"(an0) : "l"(an1));
    asm("add.rn.f32x2 %0, %0, %1;" : "+l"(at0) : "l"(at1));
    asm("add.rn.f32x2 %0, %0, %1;" : "+l"(ss0) : "l"(ss1));
    float nlo, nhi, tlo, thi, slo, shi;
    asm("mov.b64 {%0, %1}, %2;" : "=f"(nlo), "=f"(nhi) : "l"(an0));
    asm("mov.b64 {%0, %1}, %2;" : "=f"(tlo), "=f"(thi) : "l"(at0));
    asm("mov.b64 {%0, %1}, %2;" : "=f"(slo), "=f"(shi) : "l"(ss0));

    float ss   = slo + shi;
    float iac  = 1.0f / sqrtf(ss + EPSV);
    float rnt  = ss * iac * iac;
    float dotn = (nlo + nhi) * iac;
    float dott = (tlo + thi) * iac;

    float d1 = 0.5f * sqrtf(fmaxf(P.z + rnt - 2.f * dotn, 0.f) + EPSV);
    float d2 = 0.5f * sqrtf(fmaxf(P.w + rnt - 2.f * dott, 0.f) + EPSV);

    unsigned key = __float_as_uint(d1);   // positive: bit order == value order
    sk[h][col] = key;
    __syncthreads();

    // ---------- Parallel rank-count selection ----------
    // Self distance is the row minimum; ranks 1..16 = K neighbors, rank 1 = second_nn.
    int rc = 0;
    const uint4* qk = (const uint4*)sk[h];
    #pragma unroll 8
    for (int q = 0; q < NPTS / 4; q++) {
        uint4 v = qk[q];                  // broadcast LDS.128
        rc += (v.x < key) + (v.y < key) + (v.z < key) + (v.w < key);
    }

    float contrib = 0.f;
    if (rc >= 1 && rc <= KNN) {
        float df = d1 - d2;
        contrib = df * df;
        if (rc == 1) contrib += fmaxf(sh_ds[h] + 0.6f - d1, 0.f);
    }

    #pragma unroll
    for (int o = 16; o; o >>= 1) contrib += __shfl_down_sync(0xffffffffu, contrib, o);
    if (l == 0) shredf[w] = contrib;
    __syncthreads();
    if (t == 0) {
        float s = 0.f;
        #pragma unroll
        for (int m = 0; m < 16; m++) s += shredf[m];
        g_part[b] = s - 2.0f * (float)KNN * 0.0025f;
    }

    // ---------- last arriving block: deterministic final reduce ----------
    __threadfence();
    __syncthreads();
    if (t == 0) s_last = atomicAdd(&g_done, 1);
    __syncthreads();
    if (s_last == NB - 1) {
        float v = (t < NB) ? *((volatile float*)&g_part[t]) : 0.f;
        #pragma unroll
        for (int o = 16; o; o >>= 1) v += __shfl_down_sync(0xffffffffu, v, o);
        if (l == 0) shredf[w] = v;
        __syncthreads();
        if (t == 0) {
            float s = 0.f;
            #pragma unroll
            for (int m = 0; m < 16; m++) s += shredf[m];
            out[0] = s;
            *((volatile unsigned*)&g_done) = 0;   // reset for next graph replay
        }
    }
}

extern "C" void kernel_launch(void* const* d_in, const int* in_sizes, int n_in,
                              void* d_out, int out_size) {
    const float* yi  = (const float*)d_in[0];
    const float* yit = (const float*)d_in[1];
    k_fused<<<NB, 512>>>(yi, yit, (float*)d_out);
}

// round 8
// speedup vs baseline: 2.4172x; 2.4172x over previous
#include <cuda_runtime.h>
#include <stdint.h>

#define NPTS  256
#define DIM   256
#define KNN   16
#define NB    128       // 2 rows/block, independent blocks
#define EPSV  1e-12f
#define CHUNK 32        // dims staged per tile
#define NCH   (DIM / CHUNK)
#define TPAD  36        // tile row stride (floats): 32 + 4 pad -> conflict-free

__device__ float    g_part[NB];
__device__ unsigned g_done = 0;
typedef unsigned long long u64;

#define FMA2(acc, x, y) asm("fma.rn.f32x2 %0, %1, %2, %0;" : "+l"(acc) : "l"(x), "l"(y))
#define ADD2(a, b)      asm("add.rn.f32x2 %0, %0, %1;"     : "+l"(a)   : "l"(b))

__global__ __launch_bounds__(256, 1)
void k_fused(const float* __restrict__ yi, const float* __restrict__ yit,
             float* __restrict__ out) {
    __shared__ __align__(16) float s_tile[NPTS * TPAD];                  // 36 KB
    __shared__ __align__(16) float s_an0[DIM], s_cn0[DIM], s_an1[DIM], s_cn1[DIM];
    __shared__ unsigned sk0[NPTS], sk1[NPTS];
    __shared__ float4   sh4[8];
    __shared__ float2   sh2[8];
    __shared__ float    sh_sc[6];    // rn0 rn1 rt0 rt1 dself0 dself1
    __shared__ float    shred[8];
    __shared__ unsigned s_last;

    const int t = threadIdx.x, b = blockIdx.x;
    const int r0 = 2 * b, r1 = r0 + 1;
    const int w = t >> 5, l = t & 31;

    // ---------------- Phase A: normalize this block's 2 rows ----------------
    float a0 = yi [r0 * DIM + t], c0 = yit[r0 * DIM + t];
    float a1 = yi [r1 * DIM + t], c1 = yit[r1 * DIM + t];

    float4 p = make_float4(a0 * a0, c0 * c0, a1 * a1, c1 * c1);
    #pragma unroll
    for (int o = 16; o; o >>= 1) {
        p.x += __shfl_down_sync(0xffffffffu, p.x, o);
        p.y += __shfl_down_sync(0xffffffffu, p.y, o);
        p.z += __shfl_down_sync(0xffffffffu, p.z, o);
        p.w += __shfl_down_sync(0xffffffffu, p.w, o);
    }
    if (l == 0) sh4[w] = p;
    __syncthreads();
    if (w == 0) {
        float4 q = (l < 8) ? sh4[l] : make_float4(0.f, 0.f, 0.f, 0.f);
        #pragma unroll
        for (int o = 4; o; o >>= 1) {
            q.x += __shfl_down_sync(0xffffffffu, q.x, o);
            q.y += __shfl_down_sync(0xffffffffu, q.y, o);
            q.z += __shfl_down_sync(0xffffffffu, q.z, o);
            q.w += __shfl_down_sync(0xffffffffu, q.w, o);
        }
        if (l == 0) sh4[0] = q;
    }
    __syncthreads();
    float4 S = sh4[0];                    // sa0 sc0 sa1 sc1

    float ia0 = 1.0f / sqrtf(S.x + EPSV), ic0 = 1.0f / sqrtf(S.y + EPSV);
    float ia1 = 1.0f / sqrtf(S.z + EPSV), ic1 = 1.0f / sqrtf(S.w + EPSV);
    float an0 = a0 * ia0, cn0 = c0 * ic0;
    float an1 = a1 * ia1, cn1 = c1 * ic1;
    s_an0[t] = an0;  s_cn0[t] = cn0;
    s_an1[t] = an1;  s_cn1[t] = cn1;

    float d0 = an0 - cn0, d1x = an1 - cn1;
    float2 p2 = make_float2(d0 * d0, d1x * d1x);
    #pragma unroll
    for (int o = 16; o; o >>= 1) {
        p2.x += __shfl_down_sync(0xffffffffu, p2.x, o);
        p2.y += __shfl_down_sync(0xffffffffu, p2.y, o);
    }
    if (l == 0) sh2[w] = p2;
    __syncthreads();
    if (t == 0) {
        float sd0 = 0.f, sd1 = 0.f;
        #pragma unroll
        for (int m = 0; m < 8; m++) { sd0 += sh2[m].x; sd1 += sh2[m].y; }
        sh_sc[0] = S.x * ia0 * ia0;  sh_sc[1] = S.z * ia1 * ia1;
        sh_sc[2] = S.y * ic0 * ic0;  sh_sc[3] = S.w * ic1 * ic1;
        sh_sc[4] = 0.5f * sqrtf(sd0 + EPSV);
        sh_sc[5] = 0.5f * sqrtf(sd1 + EPSV);
    }
    __syncthreads();

    // ---------------- Phase B: staged-coalesced fused norm + dual dot ----------------
    // Chunk ch: stage yi[:, ch*32 .. ch*32+31] into s_tile coalesced, then each
    // thread t accumulates its column-t dot products from shared.
    const float4* yi4 = (const float4*)yi;
    const ulonglong2* pn0 = (const ulonglong2*)s_an0;
    const ulonglong2* pc0 = (const ulonglong2*)s_cn0;
    const ulonglong2* pn1 = (const ulonglong2*)s_an1;
    const ulonglong2* pc1 = (const ulonglong2*)s_cn1;

    u64 dn0x = 0, dn0y = 0, dt0x = 0, dt0y = 0;
    u64 dn1x = 0, dn1y = 0, dt1x = 0, dt1y = 0;
    u64 ssx = 0, ssy = 0;

    for (int ch = 0; ch < NCH; ch++) {
        // stage: 2048 float4 slots, 8 per thread, coalesced (4 full lines/warp/instr)
        #pragma unroll
        for (int i = 0; i < 8; i++) {
            int lin = i * 256 + t;
            int r = lin >> 3, k = lin & 7;
            float4 v = yi4[r * (DIM / 4) + ch * 8 + k];
            *(float4*)&s_tile[r * TPAD + 4 * k] = v;
        }
        __syncthreads();
        const ulonglong2* tl = (const ulonglong2*)&s_tile[t * TPAD];
        #pragma unroll
        for (int q = 0; q < 8; q++) {
            ulonglong2 v  = tl[q];               // dims (d0,d1),(d2,d3)
            ulonglong2 A0 = pn0[ch * 8 + q];     // uniform -> LDS broadcast
            ulonglong2 C0 = pc0[ch * 8 + q];
            ulonglong2 A1 = pn1[ch * 8 + q];
            ulonglong2 C1 = pc1[ch * 8 + q];
            FMA2(dn0x, A0.x, v.x);  FMA2(dn0y, A0.y, v.y);
            FMA2(dt0x, C0.x, v.x);  FMA2(dt0y, C0.y, v.y);
            FMA2(dn1x, A1.x, v.x);  FMA2(dn1y, A1.y, v.y);
            FMA2(dt1x, C1.x, v.x);  FMA2(dt1y, C1.y, v.y);
            FMA2(ssx,  v.x,  v.x);  FMA2(ssy,  v.y,  v.y);
        }
        __syncthreads();
    }

    ADD2(dn0x, dn0y);  ADD2(dt0x, dt0y);
    ADD2(dn1x, dn1y);  ADD2(dt1x, dt1y);
    ADD2(ssx,  ssy);
    float n0lo, n0hi, t0lo, t0hi, n1lo, n1hi, t1lo, t1hi, slo, shi;
    asm("mov.b64 {%0, %1}, %2;" : "=f"(n0lo), "=f"(n0hi) : "l"(dn0x));
    asm("mov.b64 {%0, %1}, %2;" : "=f"(t0lo), "=f"(t0hi) : "l"(dt0x));
    asm("mov.b64 {%0, %1}, %2;" : "=f"(n1lo), "=f"(n1hi) : "l"(dn1x));
    asm("mov.b64 {%0, %1}, %2;" : "=f"(t1lo), "=f"(t1hi) : "l"(dt1x));
    asm("mov.b64 {%0, %1}, %2;" : "=f"(slo),  "=f"(shi)  : "l"(ssx));

    float ss  = slo + shi;
    float iac = 1.0f / sqrtf(ss + EPSV);
    float rnt = ss * iac * iac;

    float rn0 = sh_sc[0], rn1 = sh_sc[1], rt0 = sh_sc[2], rt1 = sh_sc[3];
    float d1_0 = 0.5f * sqrtf(fmaxf(rn0 + rnt - 2.f * ((n0lo + n0hi) * iac), 0.f) + EPSV);
    float d2_0 = 0.5f * sqrtf(fmaxf(rt0 + rnt - 2.f * ((t0lo + t0hi) * iac), 0.f) + EPSV);
    float d1_1 = 0.5f * sqrtf(fmaxf(rn1 + rnt - 2.f * ((n1lo + n1hi) * iac), 0.f) + EPSV);
    float d2_1 = 0.5f * sqrtf(fmaxf(rt1 + rnt - 2.f * ((t1lo + t1hi) * iac), 0.f) + EPSV);

    unsigned k0 = __float_as_uint(d1_0);   // positive: bit order == value order
    unsigned k1 = __float_as_uint(d1_1);
    sk0[t] = k0;
    sk1[t] = k1;
    __syncthreads();

    // ---------------- Parallel rank-count selection ----------------
    // Self distance is the row minimum; ranks 1..16 = K neighbors, rank 1 = second_nn.
    int rc0 = 0, rc1 = 0;
    const uint4* q0 = (const uint4*)sk0;
    const uint4* q1 = (const uint4*)sk1;
    #pragma unroll 8
    for (int q = 0; q < NPTS / 4; q++) {
        uint4 v0 = q0[q];
        rc0 += (v0.x < k0) + (v0.y < k0) + (v0.z < k0) + (v0.w < k0);
        uint4 v1 = q1[q];
        rc1 += (v1.x < k1) + (v1.y < k1) + (v1.z < k1) + (v1.w < k1);
    }

    float contrib = 0.f;
    if (rc0 >= 1 && rc0 <= KNN) {
        float df = d1_0 - d2_0;
        contrib = df * df;
        if (rc0 == 1) contrib += fmaxf(sh_sc[4] + 0.6f - d1_0, 0.f);
    }
    if (rc1 >= 1 && rc1 <= KNN) {
        float df = d1_1 - d2_1;
        contrib += df * df;
        if (rc1 == 1) contrib += fmaxf(sh_sc[5] + 0.6f - d1_1, 0.f);
    }

    #pragma unroll
    for (int o = 16; o; o >>= 1) contrib += __shfl_down_sync(0xffffffffu, contrib, o);
    if (l == 0) shred[w] = contrib;
    __syncthreads();
    if (t == 0) {
        float s = 0.f;
        #pragma unroll
        for (int m = 0; m < 8; m++) s += shred[m];
        g_part[b] = s - 2.0f * (float)KNN * 0.0025f;
    }

    // ---------------- last arriving block: deterministic final reduce ----------------
    __threadfence();
    __syncthreads();
    if (t == 0) s_last = atomicAdd(&g_done, 1);
    __syncthreads();
    if (s_last == NB - 1) {
        float v = (t < NB) ? *((volatile float*)&g_part[t]) : 0.f;
        #pragma unroll
        for (int o = 16; o; o >>= 1) v += __shfl_down_sync(0xffffffffu, v, o);
        if (l == 0) shred[w] = v;
        __syncthreads();
        if (t == 0) {
            float s = 0.f;
            #pragma unroll
            for (int m = 0; m < 8; m++) s += shred[m];
            out[0] = s;
            *((volatile unsigned*)&g_done) = 0;   // reset for next graph replay
        }
    }
}

extern "C" void kernel_launch(void* const* d_in, const int* in_sizes, int n_in,
                              void* d_out, int out_size) {
    const float* yi  = (const float*)d_in[0];
    const float* yit = (const float*)d_in[1];
    k_fused<<<NB, 256>>>(yi, yit, (float*)d_out);
}

// round 9
// speedup vs baseline: 2.4213x; 1.0017x over previous
#include <cuda_runtime.h>
#include <stdint.h>

#define NPTS  256
#define DIM   256
#define KNN   16
#define NB    128       // 2 rows/block, 512 threads (h=0/1 halves), independent blocks
#define EPSV  1e-12f
#define CHUNK 32        // dims staged per tile
#define NCH   (DIM / CHUNK)
#define TPAD  36        // tile row stride (floats): 32 + 4 pad -> conflict-free

__device__ float    g_part[NB];
__device__ unsigned g_done = 0;
typedef unsigned long long u64;

#define FMA2(acc, x, y) asm("fma.rn.f32x2 %0, %1, %2, %0;" : "+l"(acc) : "l"(x), "l"(y))
#define ADD2(a, b)      asm("add.rn.f32x2 %0, %0, %1;"     : "+l"(a)   : "l"(b))

__global__ __launch_bounds__(512, 1)
void k_fused(const float* __restrict__ yi, const float* __restrict__ yit,
             float* __restrict__ out) {
    __shared__ __align__(16) float s_tile[NPTS * TPAD];          // 36 KB
    __shared__ __align__(16) float s_n[2][DIM];                  // normalized yi rows
    __shared__ __align__(16) float s_t[2][DIM];                  // normalized yit rows
    __shared__ unsigned sk[2][NPTS];
    __shared__ float    red0[16], red1[16], red2[16];
    __shared__ float4   sh_par[2];   // ia, ic, rn, rt per row
    __shared__ float    sh_ds[2];    // dself per row
    __shared__ float    shred[16];
    __shared__ unsigned s_last;

    const int t   = threadIdx.x, b = blockIdx.x;
    const int h   = t >> 8;          // which row of the pair this half handles
    const int col = t & 255;
    const int w   = t >> 5, l = t & 31;
    const int row = 2 * b + h;

    // ---------------- Phase A: normalize row `row` (3 sums, one reduction) ----------------
    float a = yi [row * DIM + col];
    float c = yit[row * DIM + col];
    float paa = a * a, pcc = c * c, pac = a * c;
    #pragma unroll
    for (int o = 16; o; o >>= 1) {
        paa += __shfl_down_sync(0xffffffffu, paa, o);
        pcc += __shfl_down_sync(0xffffffffu, pcc, o);
        pac += __shfl_down_sync(0xffffffffu, pac, o);
    }
    if (l == 0) { red0[w] = paa; red1[w] = pcc; red2[w] = pac; }
    __syncthreads();
    if (t == h * 256) {              // one thread per half
        float sa = 0.f, sc = 0.f, sac = 0.f;
        #pragma unroll
        for (int m = 0; m < 8; m++) {
            sa  += red0[h * 8 + m];
            sc  += red1[h * 8 + m];
            sac += red2[h * 8 + m];
        }
        float ia = 1.0f / sqrtf(sa + EPSV);
        float ic = 1.0f / sqrtf(sc + EPSV);
        float rn = sa * ia * ia, rt = sc * ic * ic;
        sh_par[h] = make_float4(ia, ic, rn, rt);
        sh_ds[h]  = 0.5f * sqrtf(fmaxf(rn + rt - 2.f * ia * ic * sac, 0.f) + EPSV);
    }
    __syncthreads();
    float4 P = sh_par[h];            // ia, ic, rn, rt of this half's row
    s_n[h][col] = a * P.x;
    s_t[h][col] = c * P.y;
    // (s_n/s_t writes are ordered before first compute by the staging barrier below)

    // ---------------- Phase B: staged-coalesced fused norm + dual dot ----------------
    const float4* yi4 = (const float4*)yi;
    const ulonglong2* pn = (const ulonglong2*)s_n[h];
    const ulonglong2* pc = (const ulonglong2*)s_t[h];

    u64 dnx = 0, dny = 0, dtx = 0, dty = 0, ssx = 0, ssy = 0;

    for (int ch = 0; ch < NCH; ch++) {
        // stage: 2048 float4 slots, 4 per thread, coalesced
        #pragma unroll
        for (int i = 0; i < 4; i++) {
            int lin = i * 512 + t;
            int r = lin >> 3, k = lin & 7;
            float4 v = yi4[r * (DIM / 4) + ch * 8 + k];
            *(float4*)&s_tile[r * TPAD + 4 * k] = v;
        }
        __syncthreads();
        const ulonglong2* tl = (const ulonglong2*)&s_tile[col * TPAD];
        #pragma unroll
        for (int q = 0; q < 8; q++) {
            ulonglong2 v = tl[q];                // dims (d0,d1),(d2,d3) of column `col`
            ulonglong2 A = pn[ch * 8 + q];       // warp-uniform -> LDS broadcast
            ulonglong2 C = pc[ch * 8 + q];
            FMA2(dnx, A.x, v.x);  FMA2(dny, A.y, v.y);
            FMA2(dtx, C.x, v.x);  FMA2(dty, C.y, v.y);
            FMA2(ssx, v.x, v.x);  FMA2(ssy, v.y, v.y);
        }
        __syncthreads();
    }

    ADD2(dnx, dny);  ADD2(dtx, dty);  ADD2(ssx, ssy);
    float nlo, nhi, tlo, thi, slo, shi;
    asm("mov.b64 {%0, %1}, %2;" : "=f"(nlo), "=f"(nhi) : "l"(dnx));
    asm("mov.b64 {%0, %1}, %2;" : "=f"(tlo), "=f"(thi) : "l"(dtx));
    asm("mov.b64 {%0, %1}, %2;" : "=f"(slo), "=f"(shi) : "l"(ssx));

    float ss  = slo + shi;
    float iac = 1.0f / sqrtf(ss + EPSV);
    float rnt = ss * iac * iac;
    float d1  = 0.5f * sqrtf(fmaxf(P.z + rnt - 2.f * ((nlo + nhi) * iac), 0.f) + EPSV);
    float d2  = 0.5f * sqrtf(fmaxf(P.w + rnt - 2.f * ((tlo + thi) * iac), 0.f) + EPSV);

    unsigned key = __float_as_uint(d1);   // positive: bit order == value order
    sk[h][col] = key;
    __syncthreads();

    // ---------------- Parallel rank-count selection ----------------
    // Self distance is the row minimum; ranks 1..16 = K neighbors, rank 1 = second_nn.
    int rc = 0;
    const uint4* qk = (const uint4*)sk[h];
    #pragma unroll 8
    for (int q = 0; q < NPTS / 4; q++) {
        uint4 v = qk[q];                       // broadcast LDS.128
        rc += (v.x < key) + (v.y < key) + (v.z < key) + (v.w < key);
    }

    float contrib = 0.f;
    if (rc >= 1 && rc <= KNN) {
        float df = d1 - d2;
        contrib = df * df;
        if (rc == 1) contrib += fmaxf(sh_ds[h] + 0.6f - d1, 0.f);
    }

    #pragma unroll
    for (int o = 16; o; o >>= 1) contrib += __shfl_down_sync(0xffffffffu, contrib, o);
    if (l == 0) shred[w] = contrib;
    __syncthreads();
    if (t == 0) {
        float s = 0.f;
        #pragma unroll
        for (int m = 0; m < 16; m++) s += shred[m];
        g_part[b] = s - 2.0f * (float)KNN * 0.0025f;   // both rows' -K*T
    }

    // ---------------- last arriving block: deterministic final reduce ----------------
    __threadfence();
    __syncthreads();
    if (t == 0) s_last = atomicAdd(&g_done, 1);
    __syncthreads();
    if (s_last == NB - 1) {
        float v = (t < NB) ? *((volatile float*)&g_part[t]) : 0.f;
        #pragma unroll
        for (int o = 16; o; o >>= 1) v += __shfl_down_sync(0xffffffffu, v, o);
        if (l == 0) shred[w] = v;
        __syncthreads();
        if (t == 0) {
            float s = 0.f;
            #pragma unroll
            for (int m = 0; m < 16; m++) s += shred[m];
            out[0] = s;
            *((volatile unsigned*)&g_done) = 0;   // reset for next graph replay
        }
    }
}

extern "C" void kernel_launch(void* const* d_in, const int* in_sizes, int n_in,
                              void* d_out, int out_size) {
    const float* yi  = (const float*)d_in[0];
    const float* yit = (const float*)d_in[1];
    k_fused<<<NB, 512>>>(yi, yit, (float*)d_out);
}